// round 15
// baseline (speedup 1.0000x reference)
#include <cuda_runtime.h>
#include <cuda_fp16.h>
#include <cstdint>

// ============================================================
// IndRNN on GB300: fused GEMM+scan.
//   xp tile = x @ W (fp16 mma.sync, R10 pipe-ceiling mainloop)
//   then IN-KERNEL serial scan across t, chained across CTAs via
//   decoupled-lookback flags (chunk c waits on chunk c-1 of same
//   batch/r-half). No separate scan kernel, no xp DRAM round-trip
//   (tile re-read hits L2).
// ============================================================

__device__ __half g_Wt[512 * 512];       // W^T fp16 [n][k]
__device__ __half g_xp[65536 * 512];     // xp fp16 scratch
__device__ float  g_state[2][64][256];   // h handoff per (r-half, batch)
__device__ int    g_flag[2][64][8];      // chunk-done flags

__device__ __forceinline__ uint32_t smem_u32(const void* p) {
    uint32_t a;
    asm("{ .reg .u64 t; cvta.to.shared.u64 t, %1; cvt.u32.u64 %0, t; }"
        : "=r"(a) : "l"(p));
    return a;
}

__device__ __forceinline__ void ldm_x4(uint32_t r[4], uint32_t addr) {
    asm volatile("ldmatrix.sync.aligned.m8n8.x4.shared.b16 {%0,%1,%2,%3}, [%4];"
                 : "=r"(r[0]), "=r"(r[1]), "=r"(r[2]), "=r"(r[3]) : "r"(addr));
}

__device__ __forceinline__ void mma_f16(float c[4], const uint32_t a[4],
                                        const uint32_t b0, const uint32_t b1) {
    asm volatile(
        "mma.sync.aligned.m16n8k16.row.col.f32.f16.f16.f32 "
        "{%0,%1,%2,%3}, {%4,%5,%6,%7}, {%8,%9}, {%0,%1,%2,%3};"
        : "+f"(c[0]), "+f"(c[1]), "+f"(c[2]), "+f"(c[3])
        : "r"(a[0]), "r"(a[1]), "r"(a[2]), "r"(a[3]), "r"(b0), "r"(b1));
}

__device__ __forceinline__ void cp16(uint32_t saddr, const void* g) {
    asm volatile("cp.async.cg.shared.global [%0], [%1], 16;"
                 :: "r"(saddr), "l"(g) : "memory");
}
__device__ __forceinline__ void cp_commit() {
    asm volatile("cp.async.commit_group;" ::: "memory");
}
__device__ __forceinline__ void cp_wait0() {
    asm volatile("cp.async.wait_group 0;" ::: "memory");
}

__device__ __forceinline__ uint32_t h2_bits(__half2 v) {
    return *reinterpret_cast<uint32_t*>(&v);
}

// ---------------- prepass: W transpose+fp16, clear flags ----------------
__global__ __launch_bounds__(256) void conv_w(const float* __restrict__ W) {
    int idx = blockIdx.x * blockDim.x + threadIdx.x;  // 0..262143
    int n = idx >> 9;
    int k = idx & 511;
    g_Wt[idx] = __float2half_rn(W[k * 512 + n]);
    if (idx < 2 * 64 * 8)
        (&g_flag[0][0][0])[idx] = 0;
}

// ---------------- fused GEMM + scan ----------------
// GEMM: CTA 128x256, warp 64x64, BK=32, double-buffered (R10 mainloop).
#define ROWB      80
#define A_MAT     (128 * ROWB)            // 10240
#define B_MAT     (256 * ROWB)            // 20480
#define OFF_A     0
#define OFF_B     A_MAT
#define STAGE_SZ  (A_MAT + B_MAT)         // 30720
#define GEMM_SMEM (2 * STAGE_SZ)          // 61440

__global__ __launch_bounds__(256, 1) void indrnn_fused(
    const float* __restrict__ A,      // [65536, 512]
    float* __restrict__ out,          // [65536, 512]
    const float* __restrict__ u,      // [512]
    const float* __restrict__ bias)   // [512]
{
    extern __shared__ char smem[];
    const uint32_t sb = smem_u32(smem);
    const int tid = (int)threadIdx.x;
    const int wid = tid >> 5;
    const int lane = tid & 31;

    const int bn = blockIdx.x * 256;   // r-half
    const int bm = blockIdx.y * 128;   // 128 t-rows of one batch

    const int wm = (wid & 1) * 64;
    const int wn = (wid >> 1) * 64;

    const int grp = lane >> 2;
    const int tg  = lane & 3;

    const uint32_t lrow = (uint32_t)(lane & 15);
    const uint32_t lkb  = (uint32_t)((lane >> 4) * 16);

    // A staging: thread owns 16 consecutive k of one row
    const int srow = tid >> 1;
    const int sh   = tid & 1;
    const float* aptr = A + (size_t)(bm + srow) * 512 + sh * 16;
    const uint32_t aswoff = (uint32_t)(srow * ROWB + sh * 32);

    // B staging via cp.async: thread owns one n-row
    const __half* bgp = g_Wt + (size_t)(bn + tid) * 512;
    const uint32_t bswrow = (uint32_t)(tid * ROWB);

    float acc[4][8][4];
    #pragma unroll
    for (int i = 0; i < 4; i++)
        #pragma unroll
        for (int j = 0; j < 8; j++)
            #pragma unroll
            for (int q = 0; q < 4; q++)
                acc[i][j][q] = 0.0f;

    float4 pa[4];

    // ---- prologue ----
    {
        #pragma unroll
        for (int c = 0; c < 4; c++)
            cp16(sb + OFF_B + bswrow + c * 16, bgp + c * 8);
        cp_commit();
        #pragma unroll
        for (int i = 0; i < 4; i++)
            pa[i] = reinterpret_cast<const float4*>(aptr)[i];
        const float* f = reinterpret_cast<const float*>(pa);
        uint32_t hw[8];
        #pragma unroll
        for (int i = 0; i < 8; i++)
            hw[i] = h2_bits(__floats2half2_rn(f[2 * i], f[2 * i + 1]));
        *reinterpret_cast<uint4*>(smem + OFF_A + aswoff) =
            make_uint4(hw[0], hw[1], hw[2], hw[3]);
        *reinterpret_cast<uint4*>(smem + OFF_A + aswoff + 16) =
            make_uint4(hw[4], hw[5], hw[6], hw[7]);
        cp_wait0();
    }
    __syncthreads();

    #pragma unroll 1
    for (int ch = 0; ch < 16; ch++) {
        const uint32_t st = sb + (uint32_t)(ch & 1) * STAGE_SZ;
        const uint32_t nstb = sb + (uint32_t)((ch + 1) & 1) * STAGE_SZ;

        if (ch < 15) {
            const int koff = (ch + 1) * 32;
            #pragma unroll
            for (int c = 0; c < 4; c++)
                cp16(nstb + OFF_B + bswrow + c * 16, bgp + koff + c * 8);
            cp_commit();
            #pragma unroll
            for (int i = 0; i < 4; i++)
                pa[i] = reinterpret_cast<const float4*>(aptr + koff)[i];
        }

        #pragma unroll
        for (int ks = 0; ks < 2; ks++) {
            const uint32_t kb = (uint32_t)(ks * 32) + lkb;
            uint32_t am[4][4];
            uint32_t bh[8][2];

            #pragma unroll
            for (int mb = 0; mb < 4; mb++)
                ldm_x4(am[mb], st + OFF_A +
                               (uint32_t)((wm + mb * 16 + (int)lrow) * ROWB) + kb);
            #pragma unroll
            for (int nb = 0; nb < 4; nb++) {
                uint32_t r[4];
                ldm_x4(r, st + OFF_B +
                          (uint32_t)((wn + nb * 16 + (int)lrow) * ROWB) + kb);
                bh[2 * nb][0] = r[0]; bh[2 * nb + 1][0] = r[1];
                bh[2 * nb][1] = r[2]; bh[2 * nb + 1][1] = r[3];
            }
            #pragma unroll
            for (int mb = 0; mb < 4; mb++)
                #pragma unroll
                for (int ng = 0; ng < 8; ng++)
                    mma_f16(acc[mb][ng], am[mb], bh[ng][0], bh[ng][1]);
        }

        if (ch < 15) {
            const float* f = reinterpret_cast<const float*>(pa);
            char* nst = smem + ((ch + 1) & 1) * STAGE_SZ;
            uint32_t hw[8];
            #pragma unroll
            for (int i = 0; i < 8; i++)
                hw[i] = h2_bits(__floats2half2_rn(f[2 * i], f[2 * i + 1]));
            *reinterpret_cast<uint4*>(nst + OFF_A + aswoff) =
                make_uint4(hw[0], hw[1], hw[2], hw[3]);
            *reinterpret_cast<uint4*>(nst + OFF_A + aswoff + 16) =
                make_uint4(hw[4], hw[5], hw[6], hw[7]);
            cp_wait0();
        }
        __syncthreads();
    }

    // ---- epilogue: acc -> xp tile (fp16) ----
    {
        #pragma unroll
        for (int mb = 0; mb < 4; mb++) {
            const int row0 = bm + wm + mb * 16 + grp;
            #pragma unroll
            for (int ng = 0; ng < 8; ng++) {
                const int col = bn + wn + ng * 8 + tg * 2;
                *reinterpret_cast<uint32_t*>(&g_xp[(size_t)row0 * 512 + col]) =
                    h2_bits(__floats2half2_rn(acc[mb][ng][0], acc[mb][ng][1]));
                *reinterpret_cast<uint32_t*>(&g_xp[(size_t)(row0 + 8) * 512 + col]) =
                    h2_bits(__floats2half2_rn(acc[mb][ng][2], acc[mb][ng][3]));
            }
        }
    }
    __threadfence();   // xp tile visible device-wide (own reads go via L2)
    __syncthreads();

    // ---- fused scan over this CTA's 128 t-steps ----
    {
        const int b = blockIdx.y >> 3;       // batch
        const int c = blockIdx.y & 7;        // t-chunk within batch
        const int xh = blockIdx.x;           // r-half
        const int rg = bn + tid;             // global r (thread owns one column)

        const float uu = u[rg];
        const float bb = bias[rg];

        float h;
        if (c > 0) {
            if (tid == 0) {
                while (atomicAdd(&g_flag[xh][b][c - 1], 0) == 0)
                    __nanosleep(64);
            }
            __syncthreads();
            __threadfence();                 // acquire predecessor's state
            h = g_state[xh][b][tid];
        } else {
            h = 1.0f;
        }

        const __half* ph = g_xp + (size_t)bm * 512 + rg;
        float* po = out + (size_t)bm * 512 + rg;

        #pragma unroll 1
        for (int t0 = 0; t0 < 128; t0 += 16) {
            float v[16];
            #pragma unroll
            for (int j = 0; j < 16; j++)
                v[j] = __half2float(__ldcg(ph + (size_t)(t0 + j) * 512));
            #pragma unroll
            for (int j = 0; j < 16; j++) {
                h = fmaxf(fmaf(uu, h, v[j] + bb), 0.0f);
                v[j] = h;
            }
            #pragma unroll
            for (int j = 0; j < 16; j++)
                po[(size_t)(t0 + j) * 512] = v[j];
        }

        // publish state + flag
        g_state[xh][b][tid] = h;
        __threadfence();
        __syncthreads();
        if (tid == 0)
            atomicExch(&g_flag[xh][b][c], 1);
    }
}

// ---------------- launch ----------------
extern "C" void kernel_launch(void* const* d_in, const int* in_sizes, int n_in,
                              void* d_out, int out_size)
{
    const float* x  = (const float*)d_in[0];  // [64,1024,512]
    const float* W  = (const float*)d_in[1];  // [512,512]
    const float* u  = (const float*)d_in[2];  // [512]
    const float* b  = (const float*)d_in[3];  // [512]
    float* out = (float*)d_out;               // [64,1024,512]

    (void)in_sizes; (void)n_in; (void)out_size;

    cudaFuncSetAttribute(indrnn_fused,
                         cudaFuncAttributeMaxDynamicSharedMemorySize, GEMM_SMEM);

    conv_w<<<1024, 256>>>(W);   // also clears flags

    dim3 ggrid(2, 512);  // x = r-half, y = (batch, t-chunk)
    indrnn_fused<<<ggrid, 256, GEMM_SMEM>>>(x, out, u, b);
}

// round 16
// speedup vs baseline: 1.4990x; 1.4990x over previous
#include <cuda_runtime.h>
#include <cuda_fp16.h>
#include <cstdint>

// ============================================================
// IndRNN on GB300:
//   xp = x @ W   -> FP16 mma.sync m16n8k16 (R10 pipe-ceiling GEMM)
//   out = scan(relu(xp_t + b + u*h)) in-place on fp32 xp
// R16: heterogeneous packing, no cross-CTA waits:
//   L1: GEMM batches 0-31
//   L2: scan batches 0-31 (64 CTAs) + GEMM batches 32-63 (512 CTAs)
//   L3: scan batches 32-63
// ============================================================

__device__ __half g_Wt[512 * 512];       // W^T fp16 [n][k]

__device__ __forceinline__ uint32_t smem_u32(const void* p) {
    uint32_t a;
    asm("{ .reg .u64 t; cvta.to.shared.u64 t, %1; cvt.u32.u64 %0, t; }"
        : "=r"(a) : "l"(p));
    return a;
}

__device__ __forceinline__ void ldm_x4(uint32_t r[4], uint32_t addr) {
    asm volatile("ldmatrix.sync.aligned.m8n8.x4.shared.b16 {%0,%1,%2,%3}, [%4];"
                 : "=r"(r[0]), "=r"(r[1]), "=r"(r[2]), "=r"(r[3]) : "r"(addr));
}

__device__ __forceinline__ void mma_f16(float c[4], const uint32_t a[4],
                                        const uint32_t b0, const uint32_t b1) {
    asm volatile(
        "mma.sync.aligned.m16n8k16.row.col.f32.f16.f16.f32 "
        "{%0,%1,%2,%3}, {%4,%5,%6,%7}, {%8,%9}, {%0,%1,%2,%3};"
        : "+f"(c[0]), "+f"(c[1]), "+f"(c[2]), "+f"(c[3])
        : "r"(a[0]), "r"(a[1]), "r"(a[2]), "r"(a[3]), "r"(b0), "r"(b1));
}

__device__ __forceinline__ void cp16(uint32_t saddr, const void* g) {
    asm volatile("cp.async.cg.shared.global [%0], [%1], 16;"
                 :: "r"(saddr), "l"(g) : "memory");
}
__device__ __forceinline__ void cp_commit() {
    asm volatile("cp.async.commit_group;" ::: "memory");
}
__device__ __forceinline__ void cp_wait0() {
    asm volatile("cp.async.wait_group 0;" ::: "memory");
}

__device__ __forceinline__ uint32_t h2_bits(__half2 v) {
    return *reinterpret_cast<uint32_t*>(&v);
}

// ---------------- W prepass: transpose + fp16 round ----------------
__global__ __launch_bounds__(256) void conv_w(const float* __restrict__ W) {
    int idx = blockIdx.x * blockDim.x + threadIdx.x;  // 0..262143
    int n = idx >> 9;
    int k = idx & 511;
    g_Wt[idx] = __float2half_rn(W[k * 512 + n]);
}

// ---------------- GEMM tile (R10 verbatim, parameterized) ----------------
// CTA 128x256, warp 64x64, BK=32, double-buffered, 80B padded rows.
#define ROWB      80
#define A_MAT     (128 * ROWB)            // 10240
#define B_MAT     (256 * ROWB)            // 20480
#define OFF_A     0
#define OFF_B     A_MAT
#define STAGE_SZ  (A_MAT + B_MAT)         // 30720
#define GEMM_SMEM (2 * STAGE_SZ)          // 61440

__device__ __forceinline__ void gemm_tile(
    const float* __restrict__ A, float* __restrict__ C,
    int bm, int bn, char* smem)
{
    const uint32_t sb = smem_u32(smem);
    const int tid = (int)threadIdx.x;
    const int wid = tid >> 5;
    const int lane = tid & 31;

    const int wm = (wid & 1) * 64;
    const int wn = (wid >> 1) * 64;

    const int grp = lane >> 2;
    const int tg  = lane & 3;

    const uint32_t lrow = (uint32_t)(lane & 15);
    const uint32_t lkb  = (uint32_t)((lane >> 4) * 16);

    const int srow = tid >> 1;
    const int sh   = tid & 1;
    const float* aptr = A + (size_t)(bm + srow) * 512 + sh * 16;
    const uint32_t aswoff = (uint32_t)(srow * ROWB + sh * 32);

    const __half* bgp = g_Wt + (size_t)(bn + tid) * 512;
    const uint32_t bswrow = (uint32_t)(tid * ROWB);

    float acc[4][8][4];
    #pragma unroll
    for (int i = 0; i < 4; i++)
        #pragma unroll
        for (int j = 0; j < 8; j++)
            #pragma unroll
            for (int q = 0; q < 4; q++)
                acc[i][j][q] = 0.0f;

    float4 pa[4];

    // prologue
    {
        #pragma unroll
        for (int c = 0; c < 4; c++)
            cp16(sb + OFF_B + bswrow + c * 16, bgp + c * 8);
        cp_commit();
        #pragma unroll
        for (int i = 0; i < 4; i++)
            pa[i] = reinterpret_cast<const float4*>(aptr)[i];
        const float* f = reinterpret_cast<const float*>(pa);
        uint32_t hw[8];
        #pragma unroll
        for (int i = 0; i < 8; i++)
            hw[i] = h2_bits(__floats2half2_rn(f[2 * i], f[2 * i + 1]));
        *reinterpret_cast<uint4*>(smem + OFF_A + aswoff) =
            make_uint4(hw[0], hw[1], hw[2], hw[3]);
        *reinterpret_cast<uint4*>(smem + OFF_A + aswoff + 16) =
            make_uint4(hw[4], hw[5], hw[6], hw[7]);
        cp_wait0();
    }
    __syncthreads();

    #pragma unroll 1
    for (int ch = 0; ch < 16; ch++) {
        const uint32_t st = sb + (uint32_t)(ch & 1) * STAGE_SZ;
        const uint32_t nstb = sb + (uint32_t)((ch + 1) & 1) * STAGE_SZ;

        if (ch < 15) {
            const int koff = (ch + 1) * 32;
            #pragma unroll
            for (int c = 0; c < 4; c++)
                cp16(nstb + OFF_B + bswrow + c * 16, bgp + koff + c * 8);
            cp_commit();
            #pragma unroll
            for (int i = 0; i < 4; i++)
                pa[i] = reinterpret_cast<const float4*>(aptr + koff)[i];
        }

        #pragma unroll
        for (int ks = 0; ks < 2; ks++) {
            const uint32_t kb = (uint32_t)(ks * 32) + lkb;
            uint32_t am[4][4];
            uint32_t bh[8][2];

            #pragma unroll
            for (int mb = 0; mb < 4; mb++)
                ldm_x4(am[mb], st + OFF_A +
                               (uint32_t)((wm + mb * 16 + (int)lrow) * ROWB) + kb);
            #pragma unroll
            for (int nb = 0; nb < 4; nb++) {
                uint32_t r[4];
                ldm_x4(r, st + OFF_B +
                          (uint32_t)((wn + nb * 16 + (int)lrow) * ROWB) + kb);
                bh[2 * nb][0] = r[0]; bh[2 * nb + 1][0] = r[1];
                bh[2 * nb][1] = r[2]; bh[2 * nb + 1][1] = r[3];
            }
            #pragma unroll
            for (int mb = 0; mb < 4; mb++)
                #pragma unroll
                for (int ng = 0; ng < 8; ng++)
                    mma_f16(acc[mb][ng], am[mb], bh[ng][0], bh[ng][1]);
        }

        if (ch < 15) {
            const float* f = reinterpret_cast<const float*>(pa);
            char* nst = smem + ((ch + 1) & 1) * STAGE_SZ;
            uint32_t hw[8];
            #pragma unroll
            for (int i = 0; i < 8; i++)
                hw[i] = h2_bits(__floats2half2_rn(f[2 * i], f[2 * i + 1]));
            *reinterpret_cast<uint4*>(nst + OFF_A + aswoff) =
                make_uint4(hw[0], hw[1], hw[2], hw[3]);
            *reinterpret_cast<uint4*>(nst + OFF_A + aswoff + 16) =
                make_uint4(hw[4], hw[5], hw[6], hw[7]);
            cp_wait0();
        }
        __syncthreads();
    }

    // epilogue: fp32 xp -> C
    {
        #pragma unroll
        for (int mb = 0; mb < 4; mb++) {
            const int row0 = bm + wm + mb * 16 + grp;
            #pragma unroll
            for (int ng = 0; ng < 8; ng++) {
                const int col = bn + wn + ng * 8 + tg * 2;
                *reinterpret_cast<float2*>(&C[(size_t)row0 * 512 + col]) =
                    make_float2(acc[mb][ng][0], acc[mb][ng][1]);
                *reinterpret_cast<float2*>(&C[(size_t)(row0 + 8) * 512 + col]) =
                    make_float2(acc[mb][ng][2], acc[mb][ng][3]);
            }
        }
    }
}

// ---------------- scan chain (R10 verbatim): one thread per (b, r) ----------------
__device__ __forceinline__ void scan_chain(
    float* __restrict__ xp, const float* __restrict__ u,
    const float* __restrict__ bias, int idx)
{
    const int T = 1024;
    const int R = 512;
    int b = idx >> 9;
    int r = idx & 511;

    float uu = u[r];
    float bb = bias[r];
    float h = 1.0f;
    float* p = xp + (size_t)b * T * R + r;

    #pragma unroll 1
    for (int t0 = 0; t0 < T; t0 += 32) {
        float v[32];
        #pragma unroll
        for (int j = 0; j < 32; j++)
            v[j] = p[(t0 + j) * R];
        #pragma unroll
        for (int j = 0; j < 32; j++) {
            h = fmaxf(fmaf(uu, h, v[j] + bb), 0.0f);
            v[j] = h;
        }
        #pragma unroll
        for (int j = 0; j < 32; j++)
            p[(t0 + j) * R] = v[j];
    }
}

// ---------------- kernels ----------------
// L1: GEMM batches 0-31 (m rows 0..32767). grid (2, 256).
__global__ __launch_bounds__(256, 1) void k_gemm1(
    const float* __restrict__ A, float* __restrict__ C)
{
    extern __shared__ char smem[];
    gemm_tile(A, C, blockIdx.y * 128, blockIdx.x * 256, smem);
}

// L2: bids 0..63 -> scan batches 0-31; bids 64..575 -> GEMM batches 32-63.
__global__ __launch_bounds__(256, 1) void k_mixed(
    const float* __restrict__ A, float* __restrict__ C,
    const float* __restrict__ u, const float* __restrict__ bias)
{
    extern __shared__ char smem[];
    if (blockIdx.x < 64) {
        scan_chain(C, u, bias, blockIdx.x * 256 + (int)threadIdx.x);
    } else {
        const int g = blockIdx.x - 64;          // 0..511
        gemm_tile(A, C, 32768 + (g >> 1) * 128, (g & 1) * 256, smem);
    }
}

// L3: scan batches 32-63. grid 64.
__global__ __launch_bounds__(256) void k_scan2(
    float* __restrict__ C, const float* __restrict__ u,
    const float* __restrict__ bias)
{
    scan_chain(C, u, bias, 16384 + blockIdx.x * 256 + (int)threadIdx.x);
}

// ---------------- launch ----------------
extern "C" void kernel_launch(void* const* d_in, const int* in_sizes, int n_in,
                              void* d_out, int out_size)
{
    const float* x  = (const float*)d_in[0];  // [64,1024,512]
    const float* W  = (const float*)d_in[1];  // [512,512]
    const float* u  = (const float*)d_in[2];  // [512]
    const float* b  = (const float*)d_in[3];  // [512]
    float* out = (float*)d_out;               // [64,1024,512]

    (void)in_sizes; (void)n_in; (void)out_size;

    cudaFuncSetAttribute(k_gemm1,
                         cudaFuncAttributeMaxDynamicSharedMemorySize, GEMM_SMEM);
    cudaFuncSetAttribute(k_mixed,
                         cudaFuncAttributeMaxDynamicSharedMemorySize, GEMM_SMEM);

    conv_w<<<1024, 256>>>(W);

    dim3 g1(2, 256);
    k_gemm1<<<g1, 256, GEMM_SMEM>>>(x, out);

    k_mixed<<<576, 256, GEMM_SMEM>>>(x, out, u, b);

    k_scan2<<<64, 256>>>(out, u, b);
}

// round 17
// speedup vs baseline: 1.7071x; 1.1388x over previous
#include <cuda_runtime.h>
#include <cuda_fp16.h>
#include <cstdint>

// ============================================================
// IndRNN on GB300:
//   xp = x @ W   -> FP16 mma.sync m16n8k16 (R10 pipe-ceiling GEMM)
//   out = scan(relu(xp_t + b + u*h)) in-place on fp32 xp
// R17: R10 verbatim + software-pipelined scan (double-buffered
// register batches hide DRAM latency behind the serial chain).
// ============================================================

__device__ __half g_Wt[512 * 512];       // W^T fp16 [n][k]

__device__ __forceinline__ uint32_t smem_u32(const void* p) {
    uint32_t a;
    asm("{ .reg .u64 t; cvta.to.shared.u64 t, %1; cvt.u32.u64 %0, t; }"
        : "=r"(a) : "l"(p));
    return a;
}

__device__ __forceinline__ void ldm_x4(uint32_t r[4], uint32_t addr) {
    asm volatile("ldmatrix.sync.aligned.m8n8.x4.shared.b16 {%0,%1,%2,%3}, [%4];"
                 : "=r"(r[0]), "=r"(r[1]), "=r"(r[2]), "=r"(r[3]) : "r"(addr));
}

__device__ __forceinline__ void mma_f16(float c[4], const uint32_t a[4],
                                        const uint32_t b0, const uint32_t b1) {
    asm volatile(
        "mma.sync.aligned.m16n8k16.row.col.f32.f16.f16.f32 "
        "{%0,%1,%2,%3}, {%4,%5,%6,%7}, {%8,%9}, {%0,%1,%2,%3};"
        : "+f"(c[0]), "+f"(c[1]), "+f"(c[2]), "+f"(c[3])
        : "r"(a[0]), "r"(a[1]), "r"(a[2]), "r"(a[3]), "r"(b0), "r"(b1));
}

__device__ __forceinline__ void cp16(uint32_t saddr, const void* g) {
    asm volatile("cp.async.cg.shared.global [%0], [%1], 16;"
                 :: "r"(saddr), "l"(g) : "memory");
}
__device__ __forceinline__ void cp_commit() {
    asm volatile("cp.async.commit_group;" ::: "memory");
}
__device__ __forceinline__ void cp_wait0() {
    asm volatile("cp.async.wait_group 0;" ::: "memory");
}

__device__ __forceinline__ uint32_t h2_bits(__half2 v) {
    return *reinterpret_cast<uint32_t*>(&v);
}

// ---------------- W prepass: transpose + fp16 round ----------------
__global__ __launch_bounds__(256) void conv_w(const float* __restrict__ W) {
    int idx = blockIdx.x * blockDim.x + threadIdx.x;  // 0..262143
    int n = idx >> 9;
    int k = idx & 511;
    g_Wt[idx] = __float2half_rn(W[k * 512 + n]);
}

// ---------------- FP16 GEMM: xp[65536,512] = A[65536,512] @ W ----------------
// R10 structure: CTA 128x256, warp 64x64, BK=32, double-buffered,
// cp.async for B, inline fp32->fp16 for A, 80B padded rows.
#define ROWB      80
#define A_MAT     (128 * ROWB)            // 10240
#define B_MAT     (256 * ROWB)            // 20480
#define OFF_A     0
#define OFF_B     A_MAT
#define STAGE_SZ  (A_MAT + B_MAT)         // 30720
#define GEMM_SMEM (2 * STAGE_SZ)          // 61440

__global__ __launch_bounds__(256, 1) void indrnn_gemm_f16(
    const float* __restrict__ A,   // [65536, 512]
    float* __restrict__ C)         // [65536, 512]
{
    extern __shared__ char smem[];
    const uint32_t sb = smem_u32(smem);
    const int tid = (int)threadIdx.x;
    const int wid = tid >> 5;
    const int lane = tid & 31;

    const int bn = blockIdx.x * 256;   // 2 n-tiles (W stays L2-resident)
    const int bm = blockIdx.y * 128;   // 512 m-tiles

    const int wm = (wid & 1) * 64;     // warp m-offset
    const int wn = (wid >> 1) * 64;    // warp n-offset

    const int grp = lane >> 2;         // epilogue row group
    const int tg  = lane & 3;

    const uint32_t lrow = (uint32_t)(lane & 15);
    const uint32_t lkb  = (uint32_t)((lane >> 4) * 16);

    // A staging: thread owns 16 consecutive k of one row
    const int srow = tid >> 1;         // 0..127
    const int sh   = tid & 1;
    const float* aptr = A + (size_t)(bm + srow) * 512 + sh * 16;
    const uint32_t aswoff = (uint32_t)(srow * ROWB + sh * 32);

    // B staging via cp.async: thread owns one n-row (32 halves = 4x16B)
    const __half* bgp = g_Wt + (size_t)(bn + tid) * 512;
    const uint32_t bswrow = (uint32_t)(tid * ROWB);

    float acc[4][8][4];   // [mblock][ngroup][reg] = 128 regs
    #pragma unroll
    for (int i = 0; i < 4; i++)
        #pragma unroll
        for (int j = 0; j < 8; j++)
            #pragma unroll
            for (int q = 0; q < 4; q++)
                acc[i][j][q] = 0.0f;

    float4 pa[4];  // A prefetch regs (16 fp32)

    // ---- prologue: stage 0 ----
    {
        #pragma unroll
        for (int c = 0; c < 4; c++)
            cp16(sb + OFF_B + bswrow + c * 16, bgp + c * 8);
        cp_commit();
        #pragma unroll
        for (int i = 0; i < 4; i++)
            pa[i] = reinterpret_cast<const float4*>(aptr)[i];
        const float* f = reinterpret_cast<const float*>(pa);
        uint32_t hw[8];
        #pragma unroll
        for (int i = 0; i < 8; i++)
            hw[i] = h2_bits(__floats2half2_rn(f[2 * i], f[2 * i + 1]));
        *reinterpret_cast<uint4*>(smem + OFF_A + aswoff) =
            make_uint4(hw[0], hw[1], hw[2], hw[3]);
        *reinterpret_cast<uint4*>(smem + OFF_A + aswoff + 16) =
            make_uint4(hw[4], hw[5], hw[6], hw[7]);
        cp_wait0();
    }
    __syncthreads();

    #pragma unroll 1
    for (int ch = 0; ch < 16; ch++) {
        const uint32_t st = sb + (uint32_t)(ch & 1) * STAGE_SZ;
        const uint32_t nstb = sb + (uint32_t)((ch + 1) & 1) * STAGE_SZ;

        // ---- issue next stage's loads ----
        if (ch < 15) {
            const int koff = (ch + 1) * 32;
            #pragma unroll
            for (int c = 0; c < 4; c++)
                cp16(nstb + OFF_B + bswrow + c * 16, bgp + koff + c * 8);
            cp_commit();
            #pragma unroll
            for (int i = 0; i < 4; i++)
                pa[i] = reinterpret_cast<const float4*>(aptr + koff)[i];
        }

        // ---- compute this stage: 2 k16-steps ----
        #pragma unroll
        for (int ks = 0; ks < 2; ks++) {
            const uint32_t kb = (uint32_t)(ks * 32) + lkb;
            uint32_t am[4][4];
            uint32_t bh[8][2];

            #pragma unroll
            for (int mb = 0; mb < 4; mb++)
                ldm_x4(am[mb], st + OFF_A +
                               (uint32_t)((wm + mb * 16 + (int)lrow) * ROWB) + kb);
            #pragma unroll
            for (int nb = 0; nb < 4; nb++) {
                uint32_t r[4];
                ldm_x4(r, st + OFF_B +
                          (uint32_t)((wn + nb * 16 + (int)lrow) * ROWB) + kb);
                bh[2 * nb][0] = r[0]; bh[2 * nb + 1][0] = r[1];
                bh[2 * nb][1] = r[2]; bh[2 * nb + 1][1] = r[3];
            }
            #pragma unroll
            for (int mb = 0; mb < 4; mb++)
                #pragma unroll
                for (int ng = 0; ng < 8; ng++)
                    mma_f16(acc[mb][ng], am[mb], bh[ng][0], bh[ng][1]);
        }

        // ---- convert + store next A stage ----
        if (ch < 15) {
            const float* f = reinterpret_cast<const float*>(pa);
            char* nst = smem + ((ch + 1) & 1) * STAGE_SZ;
            uint32_t hw[8];
            #pragma unroll
            for (int i = 0; i < 8; i++)
                hw[i] = h2_bits(__floats2half2_rn(f[2 * i], f[2 * i + 1]));
            *reinterpret_cast<uint4*>(nst + OFF_A + aswoff) =
                make_uint4(hw[0], hw[1], hw[2], hw[3]);
            *reinterpret_cast<uint4*>(nst + OFF_A + aswoff + 16) =
                make_uint4(hw[4], hw[5], hw[6], hw[7]);
            cp_wait0();
        }
        __syncthreads();
    }

    // ---- epilogue: acc regs -> C (fp32 xp) ----
    {
        #pragma unroll
        for (int mb = 0; mb < 4; mb++) {
            const int row0 = bm + wm + mb * 16 + grp;
            #pragma unroll
            for (int ng = 0; ng < 8; ng++) {
                const int col = bn + wn + ng * 8 + tg * 2;
                *reinterpret_cast<float2*>(&C[(size_t)row0 * 512 + col]) =
                    make_float2(acc[mb][ng][0], acc[mb][ng][1]);
                *reinterpret_cast<float2*>(&C[(size_t)(row0 + 8) * 512 + col]) =
                    make_float2(acc[mb][ng][2], acc[mb][ng][3]);
            }
        }
    }
}

// ---------------- scan: h_t = relu(xp_t + b + u*h_{t-1}), in-place ----------------
// One thread per (b, r); software-pipelined: batch i+1's loads issue
// before batch i's serial chain, hiding DRAM latency.
__global__ __launch_bounds__(256) void indrnn_scan(
    float* __restrict__ xp,          // [64, 1024, 512]
    const float* __restrict__ u,     // [512]
    const float* __restrict__ bias)  // [512]
{
    const int T = 1024;
    const int R = 512;
    int idx = blockIdx.x * blockDim.x + threadIdx.x;  // 0..32767
    int b = idx >> 9;
    int r = idx & 511;

    float uu = u[r];
    float bb = bias[r];
    float h = 1.0f;
    float* p = xp + (size_t)b * T * R + r;

    float va[32], vb[32];
    #pragma unroll
    for (int j = 0; j < 32; j++)
        va[j] = p[j * R];

    #pragma unroll 1
    for (int t0 = 0; t0 < T; t0 += 64) {
        // prefetch batch B (t0+32..t0+63)
        #pragma unroll
        for (int j = 0; j < 32; j++)
            vb[j] = p[(t0 + 32 + j) * R];
        // chain + store batch A
        #pragma unroll
        for (int j = 0; j < 32; j++) {
            h = fmaxf(fmaf(uu, h, va[j] + bb), 0.0f);
            va[j] = h;
        }
        #pragma unroll
        for (int j = 0; j < 32; j++)
            p[(t0 + j) * R] = va[j];
        // prefetch next batch A (t0+64..t0+95)
        if (t0 + 64 < T) {
            #pragma unroll
            for (int j = 0; j < 32; j++)
                va[j] = p[(t0 + 64 + j) * R];
        }
        // chain + store batch B
        #pragma unroll
        for (int j = 0; j < 32; j++) {
            h = fmaxf(fmaf(uu, h, vb[j] + bb), 0.0f);
            vb[j] = h;
        }
        #pragma unroll
        for (int j = 0; j < 32; j++)
            p[(t0 + 32 + j) * R] = vb[j];
    }
}

// ---------------- launch ----------------
extern "C" void kernel_launch(void* const* d_in, const int* in_sizes, int n_in,
                              void* d_out, int out_size)
{
    const float* x  = (const float*)d_in[0];  // [64,1024,512]
    const float* W  = (const float*)d_in[1];  // [512,512]
    const float* u  = (const float*)d_in[2];  // [512]
    const float* b  = (const float*)d_in[3];  // [512]
    float* out = (float*)d_out;               // [64,1024,512]

    (void)in_sizes; (void)n_in; (void)out_size;

    cudaFuncSetAttribute(indrnn_gemm_f16,
                         cudaFuncAttributeMaxDynamicSharedMemorySize, GEMM_SMEM);

    conv_w<<<1024, 256>>>(W);

    dim3 ggrid(2, 512);  // x = n-tile, y = m-tile
    indrnn_gemm_f16<<<ggrid, 256, GEMM_SMEM>>>(x, out);

    indrnn_scan<<<128, 256>>>(out, u, b);
}